// round 4
// baseline (speedup 1.0000x reference)
#include <cuda_runtime.h>
#include <cstdint>

// ---------------------------------------------------------------------------
// NoteAxis: 2-layer LSTM, B=4096, U=128, 128 steps, teacher-forced.
// Persistent fp32 kernel using packed fma.rn.f32x2 (2 batch rows / register).
// 128 CTAs x 256 threads; each CTA owns 32 batch rows for all steps.
// Weights pre-transposed to [k][c] once, then streamed per-chunk with
// cp.async.cg double-buffering. Gate mapping gives each thread i/f/g/o of the
// same 2 units -> cell state c stays in registers across all 128 steps.
// ---------------------------------------------------------------------------

#define B_TOTAL   4096
#define NSTEP     128
#define FDIM      127
#define UNITS     128
#define GATES     512          // 4*U
#define KDIM      256          // [x | h] concat
#define BT        32           // batch rows per CTA
#define NCTA      (B_TOTAL / BT)   // 128
#define NTHREAD   256
#define KC        32           // k rows per staged weight chunk
#define NCHUNK    (KDIM / KC)  // 8
#define ROWPAD    34           // sX row stride in floats (8B-aligned rows)
#define CHUNK_FLOATS (KC * GATES)     // 16384
#define CHUNK_BYTES  (CHUNK_FLOATS * 4) // 65536

// shared memory layout (float offsets)
#define OFF_X0    0
#define OFF_X1    (KDIM * ROWPAD)          // 8704
#define OFF_W     (2 * KDIM * ROWPAD)      // 17408
#define OFF_B0    (OFF_W + 2 * CHUNK_FLOATS) // 50176
#define OFF_B1    (OFF_B0 + GATES)
#define OFF_WO    (OFF_B1 + GATES)
#define OFF_BO    (OFF_WO + UNITS)
#define SMEM_FLOATS (OFF_BO + 4)
#define SMEM_BYTES  (SMEM_FLOATS * 4)      // ~205 KB

// ------------------ persistent device scratch (no runtime alloc) -----------
__device__ float g_Wt0[KDIM * GATES];   // layer0 weights, [k][c]
__device__ float g_Wt1[KDIM * GATES];   // layer1 weights, [k][c]
__device__ float g_b0[GATES];           // b_ih0 + b_hh0
__device__ float g_b1[GATES];
__device__ float g_wout[UNITS];
__device__ float g_bout[1];

// ---------------------------------------------------------------------------
__global__ void noteaxis_prep(const float* __restrict__ wih0, const float* __restrict__ whh0,
                              const float* __restrict__ bih0, const float* __restrict__ bhh0,
                              const float* __restrict__ wih1, const float* __restrict__ whh1,
                              const float* __restrict__ bih1, const float* __restrict__ bhh1,
                              const float* __restrict__ wout, const float* __restrict__ bout)
{
    int idx = blockIdx.x * blockDim.x + threadIdx.x;
    if (idx < KDIM * GATES) {
        int k = idx >> 9;       // 0..255
        int c = idx & 511;      // 0..511
        g_Wt0[idx] = (k < UNITS) ? wih0[c * UNITS + k] : whh0[c * UNITS + (k - UNITS)];
        g_Wt1[idx] = (k < UNITS) ? wih1[c * UNITS + k] : whh1[c * UNITS + (k - UNITS)];
    }
    if (idx < GATES) {
        g_b0[idx] = bih0[idx] + bhh0[idx];
        g_b1[idx] = bih1[idx] + bhh1[idx];
    }
    if (idx < UNITS) g_wout[idx] = wout[idx];
    if (idx == 0)    g_bout[0]   = bout[0];
}

// ---------------------------------------------------------------------------
__device__ __forceinline__ float fsig(float x) {
    // 1/(1+exp(-x)) via MUFU: rel err ~2^-22. Saturates correctly at +-inf.
    float e, r;
    asm("ex2.approx.f32 %0, %1;" : "=f"(e) : "f"(x * -1.4426950408889634f));
    asm("rcp.approx.f32 %0, %1;" : "=f"(r) : "f"(e + 1.0f));
    return r;
}
__device__ __forceinline__ float ftanh_(float x) {
    return fmaf(2.0f, fsig(2.0f * x), -1.0f);
}
__device__ __forceinline__ void unpack2(unsigned long long v, float& lo, float& hi) {
    asm("mov.b64 {%0, %1}, %2;" : "=f"(lo), "=f"(hi) : "l"(v));
}
__device__ __forceinline__ unsigned long long pack2(float lo, float hi) {
    unsigned long long v;
    asm("mov.b64 %0, {%1, %2};" : "=l"(v) : "f"(lo), "f"(hi));
    return v;
}
__device__ __forceinline__ unsigned long long dup2(float x) {
    unsigned long long v;
    asm("mov.b64 %0, {%1, %1};" : "=l"(v) : "f"(x));
    return v;
}

// Stage one 32k x 512c weight chunk (64 KB) global -> smem via cp.async.cg.
__device__ __forceinline__ void prefetch_chunk(uint32_t dst_smem, const float* __restrict__ src, int tid) {
    const char* s = reinterpret_cast<const char*>(src) + tid * 16;
    uint32_t d = dst_smem + tid * 16;
#pragma unroll
    for (int r = 0; r < 16; ++r) {
        asm volatile("cp.async.cg.shared.global [%0], [%1], 16;" :: "r"(d), "l"(s) : "memory");
        d += NTHREAD * 16;
        s += NTHREAD * 16;
    }
    asm volatile("cp.async.commit_group;" ::: "memory");
}

__device__ __forceinline__ const float* wsrc(int layer, int ch) {
    return (layer == 0 ? g_Wt0 : g_Wt1) + ch * CHUNK_FLOATS;
}

// GEMM over one 32-k chunk: acc[p][j] (+)= sum_k x2[k][pair p] * w[k][cgrp+64j]
__device__ __forceinline__ void gemm_chunk(uint32_t xrow, uint32_t wbase,
                                           unsigned long long (&acc)[4][8],
                                           int cgrp, int bgrp)
{
    uint32_t xaddr = xrow + bgrp * 8;       // byte addr of pair (bgrp) at current k
    uint32_t waddr = wbase + cgrp * 4;      // byte addr of col cgrp at current k
#pragma unroll 8
    for (int kk = 0; kk < KC; ++kk) {
        unsigned long long x0, x1, x2, x3;
        asm volatile("ld.shared.b64 %0, [%1];" : "=l"(x0) : "r"(xaddr));
        asm volatile("ld.shared.b64 %0, [%1];" : "=l"(x1) : "r"(xaddr + 32));
        asm volatile("ld.shared.b64 %0, [%1];" : "=l"(x2) : "r"(xaddr + 64));
        asm volatile("ld.shared.b64 %0, [%1];" : "=l"(x3) : "r"(xaddr + 96));
#pragma unroll
        for (int j = 0; j < 8; ++j) {
            float w;
            asm volatile("ld.shared.f32 %0, [%1];" : "=f"(w) : "r"(waddr + j * 256));
            unsigned long long wp = dup2(w);
            asm("fma.rn.f32x2 %0, %1, %2, %0;" : "+l"(acc[0][j]) : "l"(x0), "l"(wp));
            asm("fma.rn.f32x2 %0, %1, %2, %0;" : "+l"(acc[1][j]) : "l"(x1), "l"(wp));
            asm("fma.rn.f32x2 %0, %1, %2, %0;" : "+l"(acc[2][j]) : "l"(x2), "l"(wp));
            asm("fma.rn.f32x2 %0, %1, %2, %0;" : "+l"(acc[3][j]) : "l"(x3), "l"(wp));
        }
        xaddr += ROWPAD * 4;
        waddr += GATES * 4;
    }
}

// Gate nonlinearity + cell update + h store(s). acc[p][0+u]=i, [2+u]=f,
// [4+u]=g, [6+u]=o for unit u_abs = cgrp + 64u, batch pair pr = bgrp+4p.
__device__ __forceinline__ void lstm_pointwise(unsigned long long (&acc)[4][8],
                                               float (&cs)[4][2][2],
                                               uint32_t dstA, uint32_t dstB, int has_b,
                                               int cgrp, int bgrp)
{
#pragma unroll
    for (int p = 0; p < 4; ++p) {
        int pr = bgrp + 4 * p;
#pragma unroll
        for (int u = 0; u < 2; ++u) {
            float ilo, ihi, flo, fhi, glo, ghi, olo, ohi;
            unpack2(acc[p][0 + u], ilo, ihi);
            unpack2(acc[p][2 + u], flo, fhi);
            unpack2(acc[p][4 + u], glo, ghi);
            unpack2(acc[p][6 + u], olo, ohi);
            float clo = fsig(flo) * cs[p][u][0] + fsig(ilo) * ftanh_(glo);
            float chi = fsig(fhi) * cs[p][u][1] + fsig(ihi) * ftanh_(ghi);
            cs[p][u][0] = clo;
            cs[p][u][1] = chi;
            float hlo = fsig(olo) * ftanh_(clo);
            float hhi = fsig(ohi) * ftanh_(chi);
            unsigned long long hp = pack2(hlo, hhi);
            uint32_t off = (uint32_t)(((cgrp + 64 * u) * ROWPAD + 2 * pr) * 4);
            asm volatile("st.shared.b64 [%0], %1;" :: "r"(dstA + off), "l"(hp) : "memory");
            if (has_b)
                asm volatile("st.shared.b64 [%0], %1;" :: "r"(dstB + off), "l"(hp) : "memory");
        }
    }
}

// ---------------------------------------------------------------------------
__global__ void __launch_bounds__(NTHREAD, 1)
noteaxis_lstm(const float* __restrict__ nf, const float* __restrict__ tg,
              float* __restrict__ out)
{
    extern __shared__ float smem[];
    const int tid  = threadIdx.x;
    const int cgrp = tid >> 2;   // 0..63 : column group (unit pair {cgrp, cgrp+64})
    const int bgrp = tid & 3;    // 0..3  : batch-pair group
    const int b0   = blockIdx.x * BT;

    const uint32_t sbase = (uint32_t)__cvta_generic_to_shared(smem);
    const uint32_t sx0   = sbase + OFF_X0 * 4;
    const uint32_t sx1   = sbase + OFF_X1 * 4;
    const uint32_t sw    = sbase + OFF_W  * 4;

    // Kick the first weight chunk early (layer0 chunk0 -> buffer 0).
    prefetch_chunk(sw, wsrc(0, 0), tid);

    // Zero h regions (and all of sX), load biases / output weights.
    for (int i = tid; i < 2 * KDIM * ROWPAD; i += NTHREAD) smem[i] = 0.0f;
    for (int i = tid; i < GATES; i += NTHREAD) {
        smem[OFF_B0 + i] = g_b0[i];
        smem[OFF_B1 + i] = g_b1[i];
    }
    if (tid < UNITS) smem[OFF_WO + tid] = g_wout[tid];
    if (tid == 0)    smem[OFF_BO] = g_bout[0];

    float cs0[4][2][2], cs1[4][2][2];
#pragma unroll
    for (int p = 0; p < 4; ++p)
#pragma unroll
        for (int u = 0; u < 2; ++u) {
            cs0[p][u][0] = 0.0f; cs0[p][u][1] = 0.0f;
            cs1[p][u][0] = 0.0f; cs1[p][u][1] = 0.0f;
        }

    __syncthreads();   // biases + zeroed h visible before first use

    int parity = 0;    // smem weight buffer holding the next chunk to consume

    for (int t = 0; t < NSTEP; ++t) {
        // -------- stage x_t into sX0 rows 0..127 (layout [k][b]) ----------
#pragma unroll
        for (int i = 0; i < 16; ++i) {
            int idx = tid + i * NTHREAD;     // 0..4095
            int b = idx >> 7;                // 0..31
            int f = idx & 127;               // 0..127
            float v;
            if (f < FDIM)
                v = nf[((b0 + b) * NSTEP + t) * FDIM + f];
            else
                v = (t > 0) ? tg[(b0 + b) * NSTEP + (t - 1)] : 0.0f;
            smem[OFF_X0 + f * ROWPAD + b] = v;
        }

        unsigned long long acc[4][8];

        // ---------------- layer 0 : gates = [x|h0] @ Wt0 + b0 -------------
#pragma unroll
        for (int j = 0; j < 8; ++j) {
            unsigned long long bp = dup2(smem[OFF_B0 + cgrp + 64 * j]);
#pragma unroll
            for (int p = 0; p < 4; ++p) acc[p][j] = bp;
        }
        for (int ch = 0; ch < NCHUNK; ++ch) {
            int nl = (ch == NCHUNK - 1) ? 1 : 0;
            int nc = (ch == NCHUNK - 1) ? 0 : ch + 1;
            prefetch_chunk(sw + (uint32_t)(parity ^ 1) * CHUNK_BYTES, wsrc(nl, nc), tid);
            asm volatile("cp.async.wait_group 1;" ::: "memory");
            __syncthreads();                          // chunk ch + staged x visible
            gemm_chunk(sx0 + (uint32_t)(ch * KC * ROWPAD * 4),
                       sw + (uint32_t)parity * CHUNK_BYTES, acc, cgrp, bgrp);
            parity ^= 1;
            __syncthreads();                          // buffer free before overwrite
        }
        // h0 -> sX0 rows 128..255 (recurrent) and sX1 rows 0..127 (layer1 in)
        lstm_pointwise(acc, cs0, sx0 + 128 * ROWPAD * 4, sx1, 1, cgrp, bgrp);
        __syncthreads();

        // ---------------- layer 1 : gates = [h0|h1] @ Wt1 + b1 ------------
#pragma unroll
        for (int j = 0; j < 8; ++j) {
            unsigned long long bp = dup2(smem[OFF_B1 + cgrp + 64 * j]);
#pragma unroll
            for (int p = 0; p < 4; ++p) acc[p][j] = bp;
        }
        for (int ch = 0; ch < NCHUNK; ++ch) {
            int nl = (ch == NCHUNK - 1) ? 0 : 1;
            int nc = (ch == NCHUNK - 1) ? 0 : ch + 1;
            prefetch_chunk(sw + (uint32_t)(parity ^ 1) * CHUNK_BYTES, wsrc(nl, nc), tid);
            asm volatile("cp.async.wait_group 1;" ::: "memory");
            __syncthreads();
            gemm_chunk(sx1 + (uint32_t)(ch * KC * ROWPAD * 4),
                       sw + (uint32_t)parity * CHUNK_BYTES, acc, cgrp, bgrp);
            parity ^= 1;
            __syncthreads();
        }
        // h1 -> sX1 rows 128..255 (recurrent input for next step + output)
        lstm_pointwise(acc, cs1, sx1 + 128 * ROWPAD * 4, 0u, 0, cgrp, bgrp);
        __syncthreads();

        // ---------------- output: sigmoid(h1 . wout + bout) ---------------
        {
            int rowb = tid >> 3;   // 0..31
            int l8   = tid & 7;    // 0..7
            float s = 0.0f;
#pragma unroll
            for (int jj = 0; jj < 16; ++jj) {
                int u = l8 + 8 * jj;
                s += smem[OFF_X1 + (128 + u) * ROWPAD + rowb] * smem[OFF_WO + u];
            }
            s += __shfl_xor_sync(0xffffffffu, s, 1);
            s += __shfl_xor_sync(0xffffffffu, s, 2);
            s += __shfl_xor_sync(0xffffffffu, s, 4);
            if (l8 == 0)
                out[(b0 + rowb) * NSTEP + t] = fsig(s + smem[OFF_BO]);
        }
        // next-step staging only writes sX0 rows 0..127 (disjoint from the
        // sX1 h-rows read above); the chunk-loop syncs order everything else.
    }
}

// ---------------------------------------------------------------------------
extern "C" void kernel_launch(void* const* d_in, const int* in_sizes, int n_in,
                              void* d_out, int out_size)
{
    const float* nf   = (const float*)d_in[0];   // note_features [B,N,F]
    const float* tg   = (const float*)d_in[1];   // targets       [B,N]
    const float* wih0 = (const float*)d_in[2];
    const float* whh0 = (const float*)d_in[3];
    const float* bih0 = (const float*)d_in[4];
    const float* bhh0 = (const float*)d_in[5];
    const float* wih1 = (const float*)d_in[6];
    const float* whh1 = (const float*)d_in[7];
    const float* bih1 = (const float*)d_in[8];
    const float* bhh1 = (const float*)d_in[9];
    const float* wout = (const float*)d_in[10];
    const float* bout = (const float*)d_in[11];
    float* out = (float*)d_out;

    cudaFuncSetAttribute(noteaxis_lstm, cudaFuncAttributeMaxDynamicSharedMemorySize, SMEM_BYTES);

    noteaxis_prep<<<(KDIM * GATES + 255) / 256, 256>>>(wih0, whh0, bih0, bhh0,
                                                       wih1, whh1, bih1, bhh1,
                                                       wout, bout);
    noteaxis_lstm<<<NCTA, NTHREAD, SMEM_BYTES>>>(nf, tg, out);
}

// round 5
// speedup vs baseline: 1.0001x; 1.0001x over previous
#include <cuda_runtime.h>
#include <cstdint>

// ---------------------------------------------------------------------------
// NoteAxis: 2-layer LSTM, B=4096, U=128, 128 steps, teacher-forced.
// Persistent fp32 kernel using packed fma.rn.f32x2 (2 batch rows / register).
// 128 CTAs x 256 threads; each CTA owns 32 batch rows for all steps.
// Weights pre-transposed to [k][c] once, then streamed per-chunk with
// cp.async.cg double-buffering. Gate mapping gives each thread i/f/g/o of the
// same 2 units -> cell state c stays in registers across all 128 steps.
// ---------------------------------------------------------------------------

#define B_TOTAL   4096
#define NSTEP     128
#define FDIM      127
#define UNITS     128
#define GATES     512          // 4*U
#define KDIM      256          // [x | h] concat
#define BT        32           // batch rows per CTA
#define NCTA      (B_TOTAL / BT)   // 128
#define NTHREAD   256
#define KC        32           // k rows per staged weight chunk
#define NCHUNK    (KDIM / KC)  // 8
#define ROWPAD    34           // sX row stride in floats (8B-aligned rows)
#define CHUNK_FLOATS (KC * GATES)     // 16384
#define CHUNK_BYTES  (CHUNK_FLOATS * 4) // 65536

// shared memory layout (float offsets)
#define OFF_X0    0
#define OFF_X1    (KDIM * ROWPAD)          // 8704
#define OFF_W     (2 * KDIM * ROWPAD)      // 17408
#define OFF_B0    (OFF_W + 2 * CHUNK_FLOATS) // 50176
#define OFF_B1    (OFF_B0 + GATES)
#define OFF_WO    (OFF_B1 + GATES)
#define OFF_BO    (OFF_WO + UNITS)
#define SMEM_FLOATS (OFF_BO + 4)
#define SMEM_BYTES  (SMEM_FLOATS * 4)      // ~205 KB

// ------------------ persistent device scratch (no runtime alloc) -----------
__device__ float g_Wt0[KDIM * GATES];   // layer0 weights, [k][c]
__device__ float g_Wt1[KDIM * GATES];   // layer1 weights, [k][c]
__device__ float g_b0[GATES];           // b_ih0 + b_hh0
__device__ float g_b1[GATES];
__device__ float g_wout[UNITS];
__device__ float g_bout[1];

// ---------------------------------------------------------------------------
__global__ void noteaxis_prep(const float* __restrict__ wih0, const float* __restrict__ whh0,
                              const float* __restrict__ bih0, const float* __restrict__ bhh0,
                              const float* __restrict__ wih1, const float* __restrict__ whh1,
                              const float* __restrict__ bih1, const float* __restrict__ bhh1,
                              const float* __restrict__ wout, const float* __restrict__ bout)
{
    int idx = blockIdx.x * blockDim.x + threadIdx.x;
    if (idx < KDIM * GATES) {
        int k = idx >> 9;       // 0..255
        int c = idx & 511;      // 0..511
        g_Wt0[idx] = (k < UNITS) ? wih0[c * UNITS + k] : whh0[c * UNITS + (k - UNITS)];
        g_Wt1[idx] = (k < UNITS) ? wih1[c * UNITS + k] : whh1[c * UNITS + (k - UNITS)];
    }
    if (idx < GATES) {
        g_b0[idx] = bih0[idx] + bhh0[idx];
        g_b1[idx] = bih1[idx] + bhh1[idx];
    }
    if (idx < UNITS) g_wout[idx] = wout[idx];
    if (idx == 0)    g_bout[0]   = bout[0];
}

// ---------------------------------------------------------------------------
__device__ __forceinline__ float fsig(float x) {
    // 1/(1+exp(-x)) via MUFU: rel err ~2^-22. Saturates correctly at +-inf.
    float e, r;
    asm("ex2.approx.f32 %0, %1;" : "=f"(e) : "f"(x * -1.4426950408889634f));
    asm("rcp.approx.f32 %0, %1;" : "=f"(r) : "f"(e + 1.0f));
    return r;
}
__device__ __forceinline__ float ftanh_(float x) {
    return fmaf(2.0f, fsig(2.0f * x), -1.0f);
}
__device__ __forceinline__ void unpack2(unsigned long long v, float& lo, float& hi) {
    asm("mov.b64 {%0, %1}, %2;" : "=f"(lo), "=f"(hi) : "l"(v));
}
__device__ __forceinline__ unsigned long long pack2(float lo, float hi) {
    unsigned long long v;
    asm("mov.b64 %0, {%1, %2};" : "=l"(v) : "f"(lo), "f"(hi));
    return v;
}
__device__ __forceinline__ unsigned long long dup2(float x) {
    unsigned long long v;
    asm("mov.b64 %0, {%1, %1};" : "=l"(v) : "f"(x));
    return v;
}

// Stage one 32k x 512c weight chunk (64 KB) global -> smem via cp.async.cg.
__device__ __forceinline__ void prefetch_chunk(uint32_t dst_smem, const float* __restrict__ src, int tid) {
    const char* s = reinterpret_cast<const char*>(src) + tid * 16;
    uint32_t d = dst_smem + tid * 16;
#pragma unroll
    for (int r = 0; r < 16; ++r) {
        asm volatile("cp.async.cg.shared.global [%0], [%1], 16;" :: "r"(d), "l"(s) : "memory");
        d += NTHREAD * 16;
        s += NTHREAD * 16;
    }
    asm volatile("cp.async.commit_group;" ::: "memory");
}

__device__ __forceinline__ const float* wsrc(int layer, int ch) {
    return (layer == 0 ? g_Wt0 : g_Wt1) + ch * CHUNK_FLOATS;
}

// GEMM over one 32-k chunk: acc[p][j] (+)= sum_k x2[k][pair p] * w[k][cgrp+64j]
__device__ __forceinline__ void gemm_chunk(uint32_t xrow, uint32_t wbase,
                                           unsigned long long (&acc)[4][8],
                                           int cgrp, int bgrp)
{
    uint32_t xaddr = xrow + bgrp * 8;       // byte addr of pair (bgrp) at current k
    uint32_t waddr = wbase + cgrp * 4;      // byte addr of col cgrp at current k
#pragma unroll 8
    for (int kk = 0; kk < KC; ++kk) {
        unsigned long long x0, x1, x2, x3;
        asm volatile("ld.shared.b64 %0, [%1];" : "=l"(x0) : "r"(xaddr));
        asm volatile("ld.shared.b64 %0, [%1];" : "=l"(x1) : "r"(xaddr + 32));
        asm volatile("ld.shared.b64 %0, [%1];" : "=l"(x2) : "r"(xaddr + 64));
        asm volatile("ld.shared.b64 %0, [%1];" : "=l"(x3) : "r"(xaddr + 96));
#pragma unroll
        for (int j = 0; j < 8; ++j) {
            float w;
            asm volatile("ld.shared.f32 %0, [%1];" : "=f"(w) : "r"(waddr + j * 256));
            unsigned long long wp = dup2(w);
            asm("fma.rn.f32x2 %0, %1, %2, %0;" : "+l"(acc[0][j]) : "l"(x0), "l"(wp));
            asm("fma.rn.f32x2 %0, %1, %2, %0;" : "+l"(acc[1][j]) : "l"(x1), "l"(wp));
            asm("fma.rn.f32x2 %0, %1, %2, %0;" : "+l"(acc[2][j]) : "l"(x2), "l"(wp));
            asm("fma.rn.f32x2 %0, %1, %2, %0;" : "+l"(acc[3][j]) : "l"(x3), "l"(wp));
        }
        xaddr += ROWPAD * 4;
        waddr += GATES * 4;
    }
}

// Gate nonlinearity + cell update + h store(s). acc[p][0+u]=i, [2+u]=f,
// [4+u]=g, [6+u]=o for unit u_abs = cgrp + 64u, batch pair pr = bgrp+4p.
__device__ __forceinline__ void lstm_pointwise(unsigned long long (&acc)[4][8],
                                               float (&cs)[4][2][2],
                                               uint32_t dstA, uint32_t dstB, int has_b,
                                               int cgrp, int bgrp)
{
#pragma unroll
    for (int p = 0; p < 4; ++p) {
        int pr = bgrp + 4 * p;
#pragma unroll
        for (int u = 0; u < 2; ++u) {
            float ilo, ihi, flo, fhi, glo, ghi, olo, ohi;
            unpack2(acc[p][0 + u], ilo, ihi);
            unpack2(acc[p][2 + u], flo, fhi);
            unpack2(acc[p][4 + u], glo, ghi);
            unpack2(acc[p][6 + u], olo, ohi);
            float clo = fsig(flo) * cs[p][u][0] + fsig(ilo) * ftanh_(glo);
            float chi = fsig(fhi) * cs[p][u][1] + fsig(ihi) * ftanh_(ghi);
            cs[p][u][0] = clo;
            cs[p][u][1] = chi;
            float hlo = fsig(olo) * ftanh_(clo);
            float hhi = fsig(ohi) * ftanh_(chi);
            unsigned long long hp = pack2(hlo, hhi);
            uint32_t off = (uint32_t)(((cgrp + 64 * u) * ROWPAD + 2 * pr) * 4);
            asm volatile("st.shared.b64 [%0], %1;" :: "r"(dstA + off), "l"(hp) : "memory");
            if (has_b)
                asm volatile("st.shared.b64 [%0], %1;" :: "r"(dstB + off), "l"(hp) : "memory");
        }
    }
}

// ---------------------------------------------------------------------------
__global__ void __launch_bounds__(NTHREAD, 1)
noteaxis_lstm(const float* __restrict__ nf, const float* __restrict__ tg,
              float* __restrict__ out)
{
    extern __shared__ float smem[];
    const int tid  = threadIdx.x;
    const int cgrp = tid >> 2;   // 0..63 : column group (unit pair {cgrp, cgrp+64})
    const int bgrp = tid & 3;    // 0..3  : batch-pair group
    const int b0   = blockIdx.x * BT;

    const uint32_t sbase = (uint32_t)__cvta_generic_to_shared(smem);
    const uint32_t sx0   = sbase + OFF_X0 * 4;
    const uint32_t sx1   = sbase + OFF_X1 * 4;
    const uint32_t sw    = sbase + OFF_W  * 4;

    // Kick the first weight chunk early (layer0 chunk0 -> buffer 0).
    prefetch_chunk(sw, wsrc(0, 0), tid);

    // Zero h regions (and all of sX), load biases / output weights.
    for (int i = tid; i < 2 * KDIM * ROWPAD; i += NTHREAD) smem[i] = 0.0f;
    for (int i = tid; i < GATES; i += NTHREAD) {
        smem[OFF_B0 + i] = g_b0[i];
        smem[OFF_B1 + i] = g_b1[i];
    }
    if (tid < UNITS) smem[OFF_WO + tid] = g_wout[tid];
    if (tid == 0)    smem[OFF_BO] = g_bout[0];

    float cs0[4][2][2], cs1[4][2][2];
#pragma unroll
    for (int p = 0; p < 4; ++p)
#pragma unroll
        for (int u = 0; u < 2; ++u) {
            cs0[p][u][0] = 0.0f; cs0[p][u][1] = 0.0f;
            cs1[p][u][0] = 0.0f; cs1[p][u][1] = 0.0f;
        }

    __syncthreads();   // biases + zeroed h visible before first use

    int parity = 0;    // smem weight buffer holding the next chunk to consume

    for (int t = 0; t < NSTEP; ++t) {
        // -------- stage x_t into sX0 rows 0..127 (layout [k][b]) ----------
#pragma unroll
        for (int i = 0; i < 16; ++i) {
            int idx = tid + i * NTHREAD;     // 0..4095
            int b = idx >> 7;                // 0..31
            int f = idx & 127;               // 0..127
            float v;
            if (f < FDIM)
                v = nf[((b0 + b) * NSTEP + t) * FDIM + f];
            else
                v = (t > 0) ? tg[(b0 + b) * NSTEP + (t - 1)] : 0.0f;
            smem[OFF_X0 + f * ROWPAD + b] = v;
        }

        unsigned long long acc[4][8];

        // ---------------- layer 0 : gates = [x|h0] @ Wt0 + b0 -------------
#pragma unroll
        for (int j = 0; j < 8; ++j) {
            unsigned long long bp = dup2(smem[OFF_B0 + cgrp + 64 * j]);
#pragma unroll
            for (int p = 0; p < 4; ++p) acc[p][j] = bp;
        }
        for (int ch = 0; ch < NCHUNK; ++ch) {
            int nl = (ch == NCHUNK - 1) ? 1 : 0;
            int nc = (ch == NCHUNK - 1) ? 0 : ch + 1;
            prefetch_chunk(sw + (uint32_t)(parity ^ 1) * CHUNK_BYTES, wsrc(nl, nc), tid);
            asm volatile("cp.async.wait_group 1;" ::: "memory");
            __syncthreads();                          // chunk ch + staged x visible
            gemm_chunk(sx0 + (uint32_t)(ch * KC * ROWPAD * 4),
                       sw + (uint32_t)parity * CHUNK_BYTES, acc, cgrp, bgrp);
            parity ^= 1;
            __syncthreads();                          // buffer free before overwrite
        }
        // h0 -> sX0 rows 128..255 (recurrent) and sX1 rows 0..127 (layer1 in)
        lstm_pointwise(acc, cs0, sx0 + 128 * ROWPAD * 4, sx1, 1, cgrp, bgrp);
        __syncthreads();

        // ---------------- layer 1 : gates = [h0|h1] @ Wt1 + b1 ------------
#pragma unroll
        for (int j = 0; j < 8; ++j) {
            unsigned long long bp = dup2(smem[OFF_B1 + cgrp + 64 * j]);
#pragma unroll
            for (int p = 0; p < 4; ++p) acc[p][j] = bp;
        }
        for (int ch = 0; ch < NCHUNK; ++ch) {
            int nl = (ch == NCHUNK - 1) ? 0 : 1;
            int nc = (ch == NCHUNK - 1) ? 0 : ch + 1;
            prefetch_chunk(sw + (uint32_t)(parity ^ 1) * CHUNK_BYTES, wsrc(nl, nc), tid);
            asm volatile("cp.async.wait_group 1;" ::: "memory");
            __syncthreads();
            gemm_chunk(sx1 + (uint32_t)(ch * KC * ROWPAD * 4),
                       sw + (uint32_t)parity * CHUNK_BYTES, acc, cgrp, bgrp);
            parity ^= 1;
            __syncthreads();
        }
        // h1 -> sX1 rows 128..255 (recurrent input for next step + output)
        lstm_pointwise(acc, cs1, sx1 + 128 * ROWPAD * 4, 0u, 0, cgrp, bgrp);
        __syncthreads();

        // ---------------- output: sigmoid(h1 . wout + bout) ---------------
        {
            int rowb = tid >> 3;   // 0..31
            int l8   = tid & 7;    // 0..7
            float s = 0.0f;
#pragma unroll
            for (int jj = 0; jj < 16; ++jj) {
                int u = l8 + 8 * jj;
                s += smem[OFF_X1 + (128 + u) * ROWPAD + rowb] * smem[OFF_WO + u];
            }
            s += __shfl_xor_sync(0xffffffffu, s, 1);
            s += __shfl_xor_sync(0xffffffffu, s, 2);
            s += __shfl_xor_sync(0xffffffffu, s, 4);
            if (l8 == 0)
                out[(b0 + rowb) * NSTEP + t] = fsig(s + smem[OFF_BO]);
        }
        // next-step staging only writes sX0 rows 0..127 (disjoint from the
        // sX1 h-rows read above); the chunk-loop syncs order everything else.
    }
}

// ---------------------------------------------------------------------------
extern "C" void kernel_launch(void* const* d_in, const int* in_sizes, int n_in,
                              void* d_out, int out_size)
{
    const float* nf   = (const float*)d_in[0];   // note_features [B,N,F]
    const float* tg   = (const float*)d_in[1];   // targets       [B,N]
    const float* wih0 = (const float*)d_in[2];
    const float* whh0 = (const float*)d_in[3];
    const float* bih0 = (const float*)d_in[4];
    const float* bhh0 = (const float*)d_in[5];
    const float* wih1 = (const float*)d_in[6];
    const float* whh1 = (const float*)d_in[7];
    const float* bih1 = (const float*)d_in[8];
    const float* bhh1 = (const float*)d_in[9];
    const float* wout = (const float*)d_in[10];
    const float* bout = (const float*)d_in[11];
    float* out = (float*)d_out;

    cudaFuncSetAttribute(noteaxis_lstm, cudaFuncAttributeMaxDynamicSharedMemorySize, SMEM_BYTES);

    noteaxis_prep<<<(KDIM * GATES + 255) / 256, 256>>>(wih0, whh0, bih0, bhh0,
                                                       wih1, whh1, bih1, bhh1,
                                                       wout, bout);
    noteaxis_lstm<<<NCTA, NTHREAD, SMEM_BYTES>>>(nf, tg, out);
}